// round 4
// baseline (speedup 1.0000x reference)
#include <cuda_runtime.h>

#define S     32
#define SP    34
#define VOX   (S*S*S)        // 32768
#define PZ    35             // overlapping z-pair blocks
#define XSTR4 (SP*PZ*8)      // 9520 (float4 units)
#define YSTR4 (PZ*8)         // 280

// x repacked: [x:34][y:34][z0:35][c:16][zslot:2]  (pair block = 128 B aligned)
__device__ __align__(128) float g_xp2[SP*SP*PZ*32];   // 5.18 MB

// shared layout (float4 units)
#define WS_F4  1944          // 27 taps * 72 (8 cparts * 9, 1 pad slot)
#define PAR_A  1944          // 864 float4: (g00,g01,g10,g11)
#define PAR_B  2808          // 864 float4: (wlo,whi,I00b,dxy)
#define SMEM_F4 3672         // 58752 bytes

// ---------------------------------------------------------------------------
// packed f32x2 helpers
// ---------------------------------------------------------------------------
__device__ __forceinline__ unsigned long long pack2(float a, float b) {
    unsigned long long r;
    asm("mov.b64 %0, {%1, %2};" : "=l"(r) : "f"(a), "f"(b));
    return r;
}
__device__ __forceinline__ void unpack2(unsigned long long v, float& a, float& b) {
    asm("mov.b64 {%0, %1}, %2;" : "=f"(a), "=f"(b) : "l"(v));
}
__device__ __forceinline__ unsigned long long fma2(unsigned long long a,
                                                   unsigned long long b,
                                                   unsigned long long c) {
    unsigned long long d;
    asm("fma.rn.f32x2 %0, %1, %2, %3;" : "=l"(d) : "l"(a), "l"(b), "l"(c));
    return d;
}

// ---------------------------------------------------------------------------
// Pre-pass: pad + transpose x into overlapping z-pair, channels-inner layout.
// One thread per (pair block, channel-quad-pair): 8 independent loads for ILP.
// ---------------------------------------------------------------------------
__global__ void pad_pairs_kernel(const float* __restrict__ x) {
    int g = blockIdx.x * 256 + threadIdx.x;
    if (g >= SP*SP*4*PZ) return;
    int z0 = g % PZ;
    int t  = g / PZ;
    int q2 = t & 3;
    t >>= 2;
    int y  = t % SP;
    int xx = t / SP;
    bool inb_xy = (xx >= 1 && xx <= S && y >= 1 && y <= S);
    bool ib0 = inb_xy && (z0 >= 1 && z0 <= S);     // value at padded z = z0
    bool ib1 = inb_xy && (z0 <= S - 1);            // value at padded z = z0+1
    int base = (xx-1)*(S*S) + (y-1)*S;
    float4* dst = (float4*)(g_xp2 + (size_t)((xx*SP + y)*PZ + z0) * 32);
#pragma unroll
    for (int h = 0; h < 2; h++) {
        int q  = q2 + 4*h;
        int c0 = 2*q, c1 = 2*q + 1;
        float4 v;
        v.x = ib0 ? x[c0*VOX + base + z0 - 1] : 0.f;
        v.y = ib1 ? x[c0*VOX + base + z0    ] : 0.f;
        v.z = ib0 ? x[c1*VOX + base + z0 - 1] : 0.f;
        v.w = ib1 ? x[c1*VOX + base + z0    ] : 0.f;
        dst[q] = v;
    }
}

// ---------------------------------------------------------------------------
// Main kernel. CTA = 256 threads = 32 output voxels (fixed oh,ow; od 0..31).
// Phase 1: each thread computes full interp params for ~3.4 voxel-taps.
// Phase 2: 8 lanes per voxel (cpart = ci pair), packed-f32x2 conv accumulate.
// ---------------------------------------------------------------------------
__global__ void __launch_bounds__(256, 3)
deform_conv3d_kernel(const float* __restrict__ off,
                     const float* __restrict__ wgt,
                     float* __restrict__ out)
{
    extern __shared__ __align__(16) float4 sm4[];
    const int tid = threadIdx.x;
    const int vbase = blockIdx.x * 32;

    // ---- weights: sm4[t*72 + cpart*9 + q] =
    //      (w[2q][ci0], w[2q+1][ci0], w[2q][ci1], w[2q+1][ci1]), ci0=2*cpart
    for (int idx = tid; idx < 1728; idx += 256) {
        int t  = idx >> 6;
        int r  = idx & 63;
        int cp = r >> 3;
        int q  = r & 7;
        int ci0 = 2*cp, co0 = 2*q;
        float4 w;
        w.x = wgt[ co0      * 432 +  ci0      * 27 + t];
        w.y = wgt[(co0 + 1) * 432 +  ci0      * 27 + t];
        w.z = wgt[ co0      * 432 + (ci0 + 1) * 27 + t];
        w.w = wgt[(co0 + 1) * 432 + (ci0 + 1) * 27 + t];
        sm4[t*72 + cp*9 + q] = w;
    }

    // ---- phase 1: interp params for all 864 (tap, voxel) pairs of this tile
    for (int pt = tid; pt < 864; pt += 256) {
        int i   = pt & 31;
        int tix = pt >> 5;
        int v  = vbase + i;
        int oh = v >> 10, ow = (v >> 5) & 31, od = v & 31;
        int a  = tix / 9;
        int bb = (tix - 9*a) / 3;
        int cc = tix - 9*a - 3*bb;
        int aw    = a * 32 + ow;
        int w_src = aw / 3;
        int r1    = aw - 3*w_src;
        int u     = r1 * 32 + od;
        int d_src = u / 3;
        int j     = u - 3*d_src;
        int n     = 9*bb + 3*j + cc;
        int vsrc  = (oh * 32 + w_src) * 32 + d_src;

        float px = (float)(oh    + bb) + off[ n        * VOX + vsrc];
        float py = (float)(w_src + j ) + off[(n + 27) * VOX + vsrc];
        float pz = (float)(d_src + cc) + off[(n + 54) * VOX + vsrc];

        float fx = floorf(px), fy = floorf(py), fz = floorf(pz);
        int q0x = min(max((int)fx,     0), 33);
        int q1x = min(max((int)fx + 1, 0), 33);
        int q0y = min(max((int)fy,     0), 33);
        int q1y = min(max((int)fy + 1, 0), 33);
        int q0z = min(max((int)fz,     0), 33);
        int q1z = min(max((int)fz + 1, 0), 33);

        float pxm = (px < 1.f || px > 32.f) ? fx : px;
        float pym = (py < 1.f || py > 32.f) ? fy : py;
        float pzm = (pz < 1.f || pz > 32.f) ? fz : pz;
        pxm = fminf(fmaxf(pxm, 0.f), 33.f);
        pym = fminf(fmaxf(pym, 0.f), 33.f);
        pzm = fminf(fmaxf(pzm, 0.f), 33.f);

        float lx = 1.f + ((float)q0x - pxm);
        float hx = 1.f - ((float)q1x - pxm);
        float ly = 1.f + ((float)q0y - pym);
        float hy = 1.f - ((float)q1y - pym);
        float lz = 1.f + ((float)q0z - pzm);
        float hz = 1.f - ((float)q1z - pzm);

        bool  zc  = (q1z == q0z);
        float wlo = zc ? (lz + hz) : lz;
        float whi = zc ? 0.f       : hz;

        int I00b = q0x * XSTR4 + q0y * YSTR4 + q0z * 8;
        int dxy  = (((q1x - q0x) * XSTR4) << 16) | ((q1y - q0y) * YSTR4);

        sm4[PAR_A + pt] = make_float4(lx*ly, lx*hy, hx*ly, hx*hy);
        sm4[PAR_B + pt] = make_float4(wlo, whi,
                                      __int_as_float(I00b), __int_as_float(dxy));
    }
    __syncthreads();

    // ---- phase 2
    const int cpart = tid & 7;
    const int iv    = tid >> 3;
    const int v     = vbase + iv;
    const float4* __restrict__ xp = (const float4*)g_xp2;

    unsigned long long acc2[8];
#pragma unroll
    for (int k = 0; k < 8; k++) acc2[k] = 0ull;

#pragma unroll 1
    for (int t = 0; t < 27; t++) {
        float4 pa = sm4[PAR_A + t*32 + iv];
        float4 pb = sm4[PAR_B + t*32 + iv];
        int I00 = __float_as_int(pb.z) + cpart;
        int dxy = __float_as_int(pb.w);
        int dY  = dxy & 0xffff;
        int dX  = (int)(((unsigned)dxy) >> 16);

        float4 v00 = xp[I00];
        float4 v01 = xp[I00 + dY];
        float4 v10 = xp[I00 + dX];
        float4 v11 = xp[I00 + dX + dY];

        // z-combine (wlo = pb.x, whi = pb.y)
        float t00a = fmaf(pb.y, v00.y, pb.x * v00.x);
        float t00b = fmaf(pb.y, v00.w, pb.x * v00.z);
        float t01a = fmaf(pb.y, v01.y, pb.x * v01.x);
        float t01b = fmaf(pb.y, v01.w, pb.x * v01.z);
        float t10a = fmaf(pb.y, v10.y, pb.x * v10.x);
        float t10b = fmaf(pb.y, v10.w, pb.x * v10.z);
        float t11a = fmaf(pb.y, v11.y, pb.x * v11.x);
        float t11b = fmaf(pb.y, v11.w, pb.x * v11.z);

        // xy-combine
        float s0 = fmaf(pa.w, t11a, fmaf(pa.z, t10a, fmaf(pa.y, t01a, pa.x * t00a)));
        float s1 = fmaf(pa.w, t11b, fmaf(pa.z, t10b, fmaf(pa.y, t01b, pa.x * t00b)));

        unsigned long long s0p = pack2(s0, s0);
        unsigned long long s1p = pack2(s1, s1);

        // conv accumulate: acc(co-pair q) += w(ci0)*s0 + w(ci1)*s1  (packed)
        const ulonglong2* wr = (const ulonglong2*)(sm4 + t*72 + cpart*9);
#pragma unroll
        for (int q = 0; q < 8; q++) {
            ulonglong2 wq = wr[q];
            acc2[q] = fma2(wq.x, s0p, acc2[q]);
            acc2[q] = fma2(wq.y, s1p, acc2[q]);
        }
    }

    // ---- reduce partial ci sums across the 8 lanes of this voxel
    float accf[16];
#pragma unroll
    for (int k = 0; k < 8; k++) unpack2(acc2[k], accf[2*k], accf[2*k + 1]);
#pragma unroll
    for (int co = 0; co < 16; co++) {
        accf[co] += __shfl_xor_sync(0xffffffffu, accf[co], 1);
        accf[co] += __shfl_xor_sync(0xffffffffu, accf[co], 2);
        accf[co] += __shfl_xor_sync(0xffffffffu, accf[co], 4);
    }
    int co0 = 2 * cpart;
    out[ co0      * VOX + v] = accf[co0];
    out[(co0 + 1) * VOX + v] = accf[co0 + 1];
}

// ---------------------------------------------------------------------------
extern "C" void kernel_launch(void* const* d_in, const int* in_sizes, int n_in,
                              void* d_out, int out_size) {
    const float* x   = (const float*)d_in[0];   // [1,16,32,32,32]
    const float* off = (const float*)d_in[1];   // [1,81,32,32,32]
    const float* wgt = (const float*)d_in[2];   // [16,16,3,3,3]
    float* out = (float*)d_out;                 // [1,16,32,32,32]

    static int smem_set = 0;
    if (!smem_set) {
        cudaFuncSetAttribute(deform_conv3d_kernel,
                             cudaFuncAttributeMaxDynamicSharedMemorySize,
                             SMEM_F4 * 16);
        smem_set = 1;
    }

    pad_pairs_kernel<<<(SP*SP*4*PZ + 255) / 256, 256>>>(x);
    deform_conv3d_kernel<<<VOX / 32, 256, SMEM_F4 * 16>>>(off, wgt, out);
}

// round 5
// speedup vs baseline: 1.2882x; 1.2882x over previous
#include <cuda_runtime.h>

#define S     32
#define SP    34
#define VOX   (S*S*S)        // 32768
#define PZ    35             // overlapping z-pair blocks
#define XSTR4 (SP*PZ*8)      // 9520 (float4 units)
#define YSTR4 (PZ*8)         // 280

// x repacked: [x:34][y:34][z0:35][c:16][zslot:2]  (pair block = 128 B aligned)
__device__ __align__(128) float g_xp2[SP*SP*PZ*32];   // 5.18 MB

// shared layout (float4 units): weights + half-tap param double area
#define WS_BASE 0            // 1728: [t:27][q:8][cp:8]
#define PAR_A   1728         // 448:  (g00,g01,g10,g11) for up to 14 taps
#define PAR_B   2176         // 448:  (wlo,whi,I00b,dxy)
#define SMEM_F4 2624         // 41984 bytes static

// ---------------------------------------------------------------------------
// Pre-pass: pad + transpose x into overlapping z-pair, channels-inner layout.
// ---------------------------------------------------------------------------
__global__ void pad_pairs_kernel(const float* __restrict__ x) {
    int g = blockIdx.x * 256 + threadIdx.x;
    if (g >= SP*SP*4*PZ) return;
    int z0 = g % PZ;
    int t  = g / PZ;
    int q2 = t & 3;
    t >>= 2;
    int y  = t % SP;
    int xx = t / SP;
    bool inb_xy = (xx >= 1 && xx <= S && y >= 1 && y <= S);
    bool ib0 = inb_xy && (z0 >= 1 && z0 <= S);     // value at padded z = z0
    bool ib1 = inb_xy && (z0 <= S - 1);            // value at padded z = z0+1
    int base = (xx-1)*(S*S) + (y-1)*S;
    float4* dst = (float4*)(g_xp2 + (size_t)((xx*SP + y)*PZ + z0) * 32);
#pragma unroll
    for (int h = 0; h < 2; h++) {
        int q  = q2 + 4*h;
        int c0 = 2*q, c1 = 2*q + 1;
        float4 v;
        v.x = ib0 ? x[c0*VOX + base + z0 - 1] : 0.f;
        v.y = ib1 ? x[c0*VOX + base + z0    ] : 0.f;
        v.z = ib0 ? x[c1*VOX + base + z0 - 1] : 0.f;
        v.w = ib1 ? x[c1*VOX + base + z0    ] : 0.f;
        dst[q] = v;
    }
}

// ---------------------------------------------------------------------------
// Main kernel. CTA = 256 threads = 32 output voxels (fixed oh,ow; od 0..31).
// Taps processed in two blocks (14 + 13): phase1 computes interp params into
// shared once per voxel-tap; phase2 gathers + scalar-FFMA conv.
// ---------------------------------------------------------------------------
__device__ __forceinline__ void compute_params(float4* sm4,
                                               const float* __restrict__ off,
                                               int vbase, int t0, int cnt,
                                               int tid)
{
    for (int pt = tid; pt < cnt * 32; pt += 256) {
        int i   = pt & 31;
        int tix = t0 + (pt >> 5);
        int v  = vbase + i;
        int oh = v >> 10, ow = (v >> 5) & 31, od = v & 31;
        int a  = tix / 9;
        int bb = (tix - 9*a) / 3;
        int cc = tix - 9*a - 3*bb;
        int aw    = a * 32 + ow;
        int w_src = aw / 3;
        int r1    = aw - 3*w_src;
        int u     = r1 * 32 + od;
        int d_src = u / 3;
        int j     = u - 3*d_src;
        int n     = 9*bb + 3*j + cc;
        int vsrc  = (oh * 32 + w_src) * 32 + d_src;

        float px = (float)(oh    + bb) + off[ n        * VOX + vsrc];
        float py = (float)(w_src + j ) + off[(n + 27) * VOX + vsrc];
        float pz = (float)(d_src + cc) + off[(n + 54) * VOX + vsrc];

        float fx = floorf(px), fy = floorf(py), fz = floorf(pz);
        int q0x = min(max((int)fx,     0), 33);
        int q1x = min(max((int)fx + 1, 0), 33);
        int q0y = min(max((int)fy,     0), 33);
        int q1y = min(max((int)fy + 1, 0), 33);
        int q0z = min(max((int)fz,     0), 33);
        int q1z = min(max((int)fz + 1, 0), 33);

        float pxm = (px < 1.f || px > 32.f) ? fx : px;
        float pym = (py < 1.f || py > 32.f) ? fy : py;
        float pzm = (pz < 1.f || pz > 32.f) ? fz : pz;
        pxm = fminf(fmaxf(pxm, 0.f), 33.f);
        pym = fminf(fmaxf(pym, 0.f), 33.f);
        pzm = fminf(fmaxf(pzm, 0.f), 33.f);

        float lx = 1.f + ((float)q0x - pxm);
        float hx = 1.f - ((float)q1x - pxm);
        float ly = 1.f + ((float)q0y - pym);
        float hy = 1.f - ((float)q1y - pym);
        float lz = 1.f + ((float)q0z - pzm);
        float hz = 1.f - ((float)q1z - pzm);

        bool  zc  = (q1z == q0z);
        float wlo = zc ? (lz + hz) : lz;
        float whi = zc ? 0.f       : hz;

        int I00b = q0x * XSTR4 + q0y * YSTR4 + q0z * 8;
        int dxy  = (((q1x - q0x) * XSTR4) << 16) | ((q1y - q0y) * YSTR4);

        sm4[PAR_A + pt] = make_float4(lx*ly, lx*hy, hx*ly, hx*hy);
        sm4[PAR_B + pt] = make_float4(wlo, whi,
                                      __int_as_float(I00b), __int_as_float(dxy));
    }
}

__global__ void __launch_bounds__(256)
deform_conv3d_kernel(const float* __restrict__ off,
                     const float* __restrict__ wgt,
                     float* __restrict__ out)
{
    __shared__ __align__(16) float4 sm4[SMEM_F4];
    const int tid = threadIdx.x;
    const int vbase = blockIdx.x * 32;

    // ---- weights: sm4[t*64 + q*8 + cp] =
    //      (w[2q][ci0], w[2q+1][ci0], w[2q][ci1], w[2q+1][ci1]), ci0 = 2*cp
    for (int idx = tid; idx < 1728; idx += 256) {
        int t  = idx >> 6;
        int q  = (idx >> 3) & 7;
        int cp = idx & 7;
        int ci0 = 2*cp, co0 = 2*q;
        float4 w;
        w.x = wgt[ co0      * 432 +  ci0      * 27 + t];
        w.y = wgt[(co0 + 1) * 432 +  ci0      * 27 + t];
        w.z = wgt[ co0      * 432 + (ci0 + 1) * 27 + t];
        w.w = wgt[(co0 + 1) * 432 + (ci0 + 1) * 27 + t];
        sm4[WS_BASE + t*64 + q*8 + cp] = w;
    }

    const int cpart = tid & 7;
    const int iv    = tid >> 3;
    const int v     = vbase + iv;
    const float4* __restrict__ xp = (const float4*)g_xp2;

    float acc[16];
#pragma unroll
    for (int k = 0; k < 16; k++) acc[k] = 0.f;

#pragma unroll 1
    for (int half = 0; half < 2; half++) {
        int t0  = half ? 14 : 0;
        int cnt = half ? 13 : 14;

        __syncthreads();                       // params buffer free
        compute_params(sm4, off, vbase, t0, cnt, tid);
        __syncthreads();                       // params ready

#pragma unroll 1
        for (int tt = 0; tt < cnt; tt++) {
            float4 pa = sm4[PAR_A + tt*32 + iv];
            float4 pb = sm4[PAR_B + tt*32 + iv];
            int I00 = __float_as_int(pb.z) + cpart;
            int dxy = __float_as_int(pb.w);
            int dY  = dxy & 0xffff;
            int dX  = (int)(((unsigned)dxy) >> 16);

            float4 v00 = xp[I00];
            float4 v01 = xp[I00 + dY];
            float4 v10 = xp[I00 + dX];
            float4 v11 = xp[I00 + dX + dY];

            // z-combine (wlo = pb.x, whi = pb.y)
            float t00a = fmaf(pb.y, v00.y, pb.x * v00.x);
            float t00b = fmaf(pb.y, v00.w, pb.x * v00.z);
            float t01a = fmaf(pb.y, v01.y, pb.x * v01.x);
            float t01b = fmaf(pb.y, v01.w, pb.x * v01.z);
            float t10a = fmaf(pb.y, v10.y, pb.x * v10.x);
            float t10b = fmaf(pb.y, v10.w, pb.x * v10.z);
            float t11a = fmaf(pb.y, v11.y, pb.x * v11.x);
            float t11b = fmaf(pb.y, v11.w, pb.x * v11.z);

            // xy-combine
            float s0 = fmaf(pa.w, t11a, fmaf(pa.z, t10a, fmaf(pa.y, t01a, pa.x * t00a)));
            float s1 = fmaf(pa.w, t11b, fmaf(pa.z, t10b, fmaf(pa.y, t01b, pa.x * t00b)));

            // conv accumulate (scalar FFMA, conflict-free LDS.128 weights)
            const float4* wr = sm4 + WS_BASE + (t0 + tt)*64 + cpart;
#pragma unroll
            for (int q = 0; q < 8; q++) {
                float4 wq = wr[q * 8];
                acc[2*q]     = fmaf(wq.x, s0, fmaf(wq.z, s1, acc[2*q]));
                acc[2*q + 1] = fmaf(wq.y, s0, fmaf(wq.w, s1, acc[2*q + 1]));
            }
        }
    }

    // ---- reduce partial ci sums across the 8 lanes of this voxel
#pragma unroll
    for (int co = 0; co < 16; co++) {
        acc[co] += __shfl_xor_sync(0xffffffffu, acc[co], 1);
        acc[co] += __shfl_xor_sync(0xffffffffu, acc[co], 2);
        acc[co] += __shfl_xor_sync(0xffffffffu, acc[co], 4);
    }
    int co0 = 2 * cpart;
    out[ co0      * VOX + v] = acc[co0];
    out[(co0 + 1) * VOX + v] = acc[co0 + 1];
}

// ---------------------------------------------------------------------------
extern "C" void kernel_launch(void* const* d_in, const int* in_sizes, int n_in,
                              void* d_out, int out_size) {
    const float* x   = (const float*)d_in[0];   // [1,16,32,32,32]
    const float* off = (const float*)d_in[1];   // [1,81,32,32,32]
    const float* wgt = (const float*)d_in[2];   // [16,16,3,3,3]
    float* out = (float*)d_out;                 // [1,16,32,32,32]

    pad_pairs_kernel<<<(SP*SP*4*PZ + 255) / 256, 256>>>(x);
    deform_conv3d_kernel<<<VOX / 32, 256>>>(off, wgt, out);
}

// round 9
// speedup vs baseline: 1.3548x; 1.0517x over previous
#include <cuda_runtime.h>

#define S     32
#define SP    34
#define VOX   (S*S*S)        // 32768
#define PZ    35             // overlapping z-pair blocks
#define XSTR4 (SP*PZ*8)      // 9520 (float4 units)
#define YSTR4 (PZ*8)         // 280

// x repacked: [x:34][y:34][z0:35][c:16][zslot:2]  (pair block = 128 B aligned)
__device__ __align__(128) float g_xp2[SP*SP*PZ*32];   // 5.18 MB

// dynamic shared layout (float4 units)
#define WS_BASE 0            // 1728: [t:27][q:8][cp:8]
#define PAR_A   1728         // 864: (g00,g01,g10,g11)   [t:27][i:32]
#define PAR_B   2592         // 864: (wlo,whi,I00b,dxy)  [t:27][i:32]
#define SMEM_F4 3456         // 55296 bytes

// ---------------------------------------------------------------------------
// Pre-pass: pad + transpose x into overlapping z-pair, channels-inner layout.
// q fastest across lanes -> 8 lanes write one contiguous 128B block (coalesced).
// ---------------------------------------------------------------------------
__global__ void pad_pairs_kernel(const float* __restrict__ x) {
    int g = blockIdx.x * 256 + threadIdx.x;
    if (g >= SP*SP*PZ*8) return;
    int q  = g & 7;            // channel pair {2q, 2q+1}
    int sp = g >> 3;           // pair block (x,y,z0), z0 fastest
    int z0 = sp % PZ;
    int t  = sp / PZ;
    int y  = t % SP;
    int xx = t / SP;
    bool inb_xy = (xx >= 1 && xx <= S && y >= 1 && y <= S);
    bool ib0 = inb_xy && (z0 >= 1 && z0 <= S);     // value at padded z = z0
    bool ib1 = inb_xy && (z0 <= S - 1);            // value at padded z = z0+1
    int base = (xx-1)*(S*S) + (y-1)*S;
    int c0 = 2*q, c1 = 2*q + 1;
    float4 v;
    v.x = ib0 ? x[c0*VOX + base + z0 - 1] : 0.f;
    v.y = ib1 ? x[c0*VOX + base + z0    ] : 0.f;
    v.z = ib0 ? x[c1*VOX + base + z0 - 1] : 0.f;
    v.w = ib1 ? x[c1*VOX + base + z0    ] : 0.f;
    ((float4*)g_xp2)[(size_t)sp * 8 + q] = v;
}

// ---------------------------------------------------------------------------
// Main kernel. CTA = 256 threads = 32 output voxels (fixed oh,ow; od 0..31).
// Phase 1: interp params for all 27 taps -> shared (computed once).
// Phase 2: software-pipelined gather + scalar-FFMA conv (MLP 8).
// ---------------------------------------------------------------------------
__global__ void __launch_bounds__(256)
deform_conv3d_kernel(const float* __restrict__ off,
                     const float* __restrict__ wgt,
                     float* __restrict__ out)
{
    extern __shared__ __align__(16) float4 sm4[];
    const int tid = threadIdx.x;
    const int vbase = blockIdx.x * 32;

    // ---- weights: sm4[t*64 + q*8 + cp] =
    //      (w[2q][ci0], w[2q+1][ci0], w[2q][ci1], w[2q+1][ci1]), ci0 = 2*cp
    for (int idx = tid; idx < 1728; idx += 256) {
        int t  = idx >> 6;
        int q  = (idx >> 3) & 7;
        int cp = idx & 7;
        int ci0 = 2*cp, co0 = 2*q;
        float4 w;
        w.x = wgt[ co0      * 432 +  ci0      * 27 + t];
        w.y = wgt[(co0 + 1) * 432 +  ci0      * 27 + t];
        w.z = wgt[ co0      * 432 + (ci0 + 1) * 27 + t];
        w.w = wgt[(co0 + 1) * 432 + (ci0 + 1) * 27 + t];
        sm4[WS_BASE + t*64 + q*8 + cp] = w;
    }

    // ---- phase 1: params for all 864 (tap, voxel) pairs of this tile
    for (int pt = tid; pt < 864; pt += 256) {
        int i   = pt & 31;
        int tix = pt >> 5;
        int v  = vbase + i;
        int oh = v >> 10, ow = (v >> 5) & 31, od = v & 31;
        int a  = tix / 9;
        int bb = (tix - 9*a) / 3;
        int cc = tix - 9*a - 3*bb;
        int aw    = a * 32 + ow;
        int w_src = aw / 3;
        int r1    = aw - 3*w_src;
        int u     = r1 * 32 + od;
        int d_src = u / 3;
        int j     = u - 3*d_src;
        int n     = 9*bb + 3*j + cc;
        int vsrc  = (oh * 32 + w_src) * 32 + d_src;

        float px = (float)(oh    + bb) + off[ n        * VOX + vsrc];
        float py = (float)(w_src + j ) + off[(n + 27) * VOX + vsrc];
        float pz = (float)(d_src + cc) + off[(n + 54) * VOX + vsrc];

        float fx = floorf(px), fy = floorf(py), fz = floorf(pz);
        int q0x = min(max((int)fx,     0), 33);
        int q1x = min(max((int)fx + 1, 0), 33);
        int q0y = min(max((int)fy,     0), 33);
        int q1y = min(max((int)fy + 1, 0), 33);
        int q0z = min(max((int)fz,     0), 33);
        int q1z = min(max((int)fz + 1, 0), 33);

        float pxm = (px < 1.f || px > 32.f) ? fx : px;
        float pym = (py < 1.f || py > 32.f) ? fy : py;
        float pzm = (pz < 1.f || pz > 32.f) ? fz : pz;
        pxm = fminf(fmaxf(pxm, 0.f), 33.f);
        pym = fminf(fmaxf(pym, 0.f), 33.f);
        pzm = fminf(fmaxf(pzm, 0.f), 33.f);

        float lx = 1.f + ((float)q0x - pxm);
        float hx = 1.f - ((float)q1x - pxm);
        float ly = 1.f + ((float)q0y - pym);
        float hy = 1.f - ((float)q1y - pym);
        float lz = 1.f + ((float)q0z - pzm);
        float hz = 1.f - ((float)q1z - pzm);

        bool  zc  = (q1z == q0z);
        float wlo = zc ? (lz + hz) : lz;
        float whi = zc ? 0.f       : hz;

        int I00b = q0x * XSTR4 + q0y * YSTR4 + q0z * 8;
        int dxy  = (((q1x - q0x) * XSTR4) << 16) | ((q1y - q0y) * YSTR4);

        sm4[PAR_A + pt] = make_float4(lx*ly, lx*hy, hx*ly, hx*hy);
        sm4[PAR_B + pt] = make_float4(wlo, whi,
                                      __int_as_float(I00b), __int_as_float(dxy));
    }
    __syncthreads();

    // ---- phase 2 (double-buffered over taps)
    const int cpart = tid & 7;
    const int iv    = tid >> 3;
    const int v     = vbase + iv;
    const float4* __restrict__ xp = (const float4*)g_xp2;

    float acc[16];
#pragma unroll
    for (int k = 0; k < 16; k++) acc[k] = 0.f;

    // prologue: tap 0
    float4 pa = sm4[PAR_A + iv];
    float4 pb = sm4[PAR_B + iv];
    int I00, dX, dY;
    {
        I00 = __float_as_int(pb.z) + cpart;
        int dxy = __float_as_int(pb.w);
        dY = dxy & 0xffff;
        dX = (int)(((unsigned)dxy) >> 16);
    }
    float4 c00 = xp[I00];
    float4 c01 = xp[I00 + dY];
    float4 c10 = xp[I00 + dX];
    float4 c11 = xp[I00 + dX + dY];

#pragma unroll 1
    for (int t = 0; t < 27; t++) {
        // prefetch tap t+1 (tail reloads tap 26 harmlessly)
        int tn = (t < 26) ? t + 1 : 26;
        float4 npa = sm4[PAR_A + tn*32 + iv];
        float4 npb = sm4[PAR_B + tn*32 + iv];
        int nI00 = __float_as_int(npb.z) + cpart;
        int ndxy = __float_as_int(npb.w);
        int ndY  = ndxy & 0xffff;
        int ndX  = (int)(((unsigned)ndxy) >> 16);
        float4 n00 = xp[nI00];
        float4 n01 = xp[nI00 + ndY];
        float4 n10 = xp[nI00 + ndX];
        float4 n11 = xp[nI00 + ndX + ndY];

        // ---- compute tap t ----
        // z-combine (wlo = pb.x, whi = pb.y)
        float t00a = fmaf(pb.y, c00.y, pb.x * c00.x);
        float t00b = fmaf(pb.y, c00.w, pb.x * c00.z);
        float t01a = fmaf(pb.y, c01.y, pb.x * c01.x);
        float t01b = fmaf(pb.y, c01.w, pb.x * c01.z);
        float t10a = fmaf(pb.y, c10.y, pb.x * c10.x);
        float t10b = fmaf(pb.y, c10.w, pb.x * c10.z);
        float t11a = fmaf(pb.y, c11.y, pb.x * c11.x);
        float t11b = fmaf(pb.y, c11.w, pb.x * c11.z);
        // xy-combine
        float s0 = fmaf(pa.w, t11a, fmaf(pa.z, t10a, fmaf(pa.y, t01a, pa.x * t00a)));
        float s1 = fmaf(pa.w, t11b, fmaf(pa.z, t10b, fmaf(pa.y, t01b, pa.x * t00b)));

        // conv accumulate (scalar FFMA, conflict-free LDS.128 weights)
        const float4* wr = sm4 + WS_BASE + t*64 + cpart;
#pragma unroll
        for (int q = 0; q < 8; q++) {
            float4 wq = wr[q * 8];
            acc[2*q]     = fmaf(wq.x, s0, fmaf(wq.z, s1, acc[2*q]));
            acc[2*q + 1] = fmaf(wq.y, s0, fmaf(wq.w, s1, acc[2*q + 1]));
        }

        // rotate buffers
        pa = npa; pb = npb;
        c00 = n00; c01 = n01; c10 = n10; c11 = n11;
    }

    // ---- reduce partial ci sums across the 8 lanes of this voxel
#pragma unroll
    for (int co = 0; co < 16; co++) {
        acc[co] += __shfl_xor_sync(0xffffffffu, acc[co], 1);
        acc[co] += __shfl_xor_sync(0xffffffffu, acc[co], 2);
        acc[co] += __shfl_xor_sync(0xffffffffu, acc[co], 4);
    }
    int co0 = 2 * cpart;
    out[ co0      * VOX + v] = acc[co0];
    out[(co0 + 1) * VOX + v] = acc[co0 + 1];
}

// ---------------------------------------------------------------------------
extern "C" void kernel_launch(void* const* d_in, const int* in_sizes, int n_in,
                              void* d_out, int out_size) {
    const float* x   = (const float*)d_in[0];   // [1,16,32,32,32]
    const float* off = (const float*)d_in[1];   // [1,81,32,32,32]
    const float* wgt = (const float*)d_in[2];   // [16,16,3,3,3]
    float* out = (float*)d_out;                 // [1,16,32,32,32]

    cudaFuncSetAttribute(deform_conv3d_kernel,
                         cudaFuncAttributeMaxDynamicSharedMemorySize,
                         SMEM_F4 * 16);

    pad_pairs_kernel<<<(SP*SP*PZ*8 + 255) / 256, 256>>>(x);
    deform_conv3d_kernel<<<VOX / 32, 256, SMEM_F4 * 16>>>(off, wgt, out);
}

// round 10
// speedup vs baseline: 1.7610x; 1.2998x over previous
#include <cuda_runtime.h>

#define S     32
#define SP    34
#define VOX   (S*S*S)        // 32768
#define PZ    35             // overlapping z-pair blocks
#define XSTR4 (SP*PZ*8)      // 9520 (float4 units)
#define YSTR4 (PZ*8)         // 280

// x repacked: [x:34][y:34][z0:35][c:16][zslot:2]  (pair block = 128 B aligned)
__device__ __align__(128) float g_xp2[SP*SP*PZ*32];   // 5.18 MB

// dynamic shared layout (float4 units)
#define WS_BASE 0            // 1728: [t:27][q:8][cp:8]
#define PAR_A   1728         // 1728: (g00,g01,g10,g11)   [t:27][i:64]
#define PAR_B   3456         // 1728: (wlo,whi,I00b,dxy)  [t:27][i:64]
#define SMEM_F4 5184         // 82944 bytes

// ---------------------------------------------------------------------------
// Pre-pass: pad + transpose x into overlapping z-pair, channels-inner layout.
// ---------------------------------------------------------------------------
__global__ void pad_pairs_kernel(const float* __restrict__ x) {
    int g = blockIdx.x * 256 + threadIdx.x;
    if (g >= SP*SP*PZ*8) return;
    int q  = g & 7;            // channel pair {2q, 2q+1}
    int sp = g >> 3;           // pair block (x,y,z0), z0 fastest
    int z0 = sp % PZ;
    int t  = sp / PZ;
    int y  = t % SP;
    int xx = t / SP;
    bool inb_xy = (xx >= 1 && xx <= S && y >= 1 && y <= S);
    bool ib0 = inb_xy && (z0 >= 1 && z0 <= S);     // value at padded z = z0
    bool ib1 = inb_xy && (z0 <= S - 1);            // value at padded z = z0+1
    int base = (xx-1)*(S*S) + (y-1)*S;
    int c0 = 2*q, c1 = 2*q + 1;
    float4 v;
    v.x = ib0 ? x[c0*VOX + base + z0 - 1] : 0.f;
    v.y = ib1 ? x[c0*VOX + base + z0    ] : 0.f;
    v.z = ib0 ? x[c1*VOX + base + z0 - 1] : 0.f;
    v.w = ib1 ? x[c1*VOX + base + z0    ] : 0.f;
    ((float4*)g_xp2)[(size_t)sp * 8 + q] = v;
}

// ---------------------------------------------------------------------------
// Main kernel. CTA = 256 threads = 64 output voxels; each lane handles TWO
// voxels (v, v+32) so each weight LDS.128 serves 8 voxels per warp.
// Phase 1: interp params for all 27 taps x 64 voxels -> shared.
// Phase 2: gather + scalar-FFMA conv, weights amortized x2.
// ---------------------------------------------------------------------------
__global__ void __launch_bounds__(256)
deform_conv3d_kernel(const float* __restrict__ off,
                     const float* __restrict__ wgt,
                     float* __restrict__ out)
{
    extern __shared__ __align__(16) float4 sm4[];
    const int tid = threadIdx.x;
    const int vbase = blockIdx.x * 64;

    // ---- weights: sm4[t*64 + q*8 + cp] =
    //      (w[2q][ci0], w[2q+1][ci0], w[2q][ci1], w[2q+1][ci1]), ci0 = 2*cp
    for (int idx = tid; idx < 1728; idx += 256) {
        int t  = idx >> 6;
        int q  = (idx >> 3) & 7;
        int cp = idx & 7;
        int ci0 = 2*cp, co0 = 2*q;
        float4 w;
        w.x = wgt[ co0      * 432 +  ci0      * 27 + t];
        w.y = wgt[(co0 + 1) * 432 +  ci0      * 27 + t];
        w.z = wgt[ co0      * 432 + (ci0 + 1) * 27 + t];
        w.w = wgt[(co0 + 1) * 432 + (ci0 + 1) * 27 + t];
        sm4[WS_BASE + t*64 + q*8 + cp] = w;
    }

    // ---- phase 1: params for all 1728 (tap, voxel) pairs of this tile
    for (int pt = tid; pt < 1728; pt += 256) {
        int i   = pt & 63;
        int tix = pt >> 6;
        int v  = vbase + i;
        int oh = v >> 10, ow = (v >> 5) & 31, od = v & 31;
        int a  = tix / 9;
        int bb = (tix - 9*a) / 3;
        int cc = tix - 9*a - 3*bb;
        int aw    = a * 32 + ow;
        int w_src = aw / 3;
        int r1    = aw - 3*w_src;
        int u     = r1 * 32 + od;
        int d_src = u / 3;
        int j     = u - 3*d_src;
        int n     = 9*bb + 3*j + cc;
        int vsrc  = (oh * 32 + w_src) * 32 + d_src;

        float px = (float)(oh    + bb) + off[ n        * VOX + vsrc];
        float py = (float)(w_src + j ) + off[(n + 27) * VOX + vsrc];
        float pz = (float)(d_src + cc) + off[(n + 54) * VOX + vsrc];

        float fx = floorf(px), fy = floorf(py), fz = floorf(pz);
        int q0x = min(max((int)fx,     0), 33);
        int q1x = min(max((int)fx + 1, 0), 33);
        int q0y = min(max((int)fy,     0), 33);
        int q1y = min(max((int)fy + 1, 0), 33);
        int q0z = min(max((int)fz,     0), 33);
        int q1z = min(max((int)fz + 1, 0), 33);

        float pxm = (px < 1.f || px > 32.f) ? fx : px;
        float pym = (py < 1.f || py > 32.f) ? fy : py;
        float pzm = (pz < 1.f || pz > 32.f) ? fz : pz;
        pxm = fminf(fmaxf(pxm, 0.f), 33.f);
        pym = fminf(fmaxf(pym, 0.f), 33.f);
        pzm = fminf(fmaxf(pzm, 0.f), 33.f);

        float lx = 1.f + ((float)q0x - pxm);
        float hx = 1.f - ((float)q1x - pxm);
        float ly = 1.f + ((float)q0y - pym);
        float hy = 1.f - ((float)q1y - pym);
        float lz = 1.f + ((float)q0z - pzm);
        float hz = 1.f - ((float)q1z - pzm);

        bool  zc  = (q1z == q0z);
        float wlo = zc ? (lz + hz) : lz;
        float whi = zc ? 0.f       : hz;

        int I00b = q0x * XSTR4 + q0y * YSTR4 + q0z * 8;
        int dxy  = (((q1x - q0x) * XSTR4) << 16) | ((q1y - q0y) * YSTR4);

        sm4[PAR_A + pt] = make_float4(lx*ly, lx*hy, hx*ly, hx*hy);
        sm4[PAR_B + pt] = make_float4(wlo, whi,
                                      __int_as_float(I00b), __int_as_float(dxy));
    }
    __syncthreads();

    // ---- phase 2: each lane owns voxels (vbase+iv) and (vbase+iv+32)
    const int cpart = tid & 7;
    const int iv    = tid >> 3;          // 0..31
    const int vA    = vbase + iv;
    const int vB    = vA + 32;
    const float4* __restrict__ xp = (const float4*)g_xp2;

    float accA[16], accB[16];
#pragma unroll
    for (int k = 0; k < 16; k++) { accA[k] = 0.f; accB[k] = 0.f; }

#pragma unroll 1
    for (int t = 0; t < 27; t++) {
        // voxel A params + corners
        float4 paA = sm4[PAR_A + t*64 + iv];
        float4 pbA = sm4[PAR_B + t*64 + iv];
        int IA  = __float_as_int(pbA.z) + cpart;
        int dxyA = __float_as_int(pbA.w);
        int dYA = dxyA & 0xffff;
        int dXA = (int)(((unsigned)dxyA) >> 16);
        float4 a00 = xp[IA];
        float4 a01 = xp[IA + dYA];
        float4 a10 = xp[IA + dXA];
        float4 a11 = xp[IA + dXA + dYA];

        // voxel B params + corners
        float4 paB = sm4[PAR_A + t*64 + iv + 32];
        float4 pbB = sm4[PAR_B + t*64 + iv + 32];
        int IB  = __float_as_int(pbB.z) + cpart;
        int dxyB = __float_as_int(pbB.w);
        int dYB = dxyB & 0xffff;
        int dXB = (int)(((unsigned)dxyB) >> 16);
        float4 b00 = xp[IB];
        float4 b01 = xp[IB + dYB];
        float4 b10 = xp[IB + dXB];
        float4 b11 = xp[IB + dXB + dYB];

        // interp voxel A
        float tA00a = fmaf(pbA.y, a00.y, pbA.x * a00.x);
        float tA00b = fmaf(pbA.y, a00.w, pbA.x * a00.z);
        float tA01a = fmaf(pbA.y, a01.y, pbA.x * a01.x);
        float tA01b = fmaf(pbA.y, a01.w, pbA.x * a01.z);
        float tA10a = fmaf(pbA.y, a10.y, pbA.x * a10.x);
        float tA10b = fmaf(pbA.y, a10.w, pbA.x * a10.z);
        float tA11a = fmaf(pbA.y, a11.y, pbA.x * a11.x);
        float tA11b = fmaf(pbA.y, a11.w, pbA.x * a11.z);
        float sA0 = fmaf(paA.w, tA11a, fmaf(paA.z, tA10a, fmaf(paA.y, tA01a, paA.x * tA00a)));
        float sA1 = fmaf(paA.w, tA11b, fmaf(paA.z, tA10b, fmaf(paA.y, tA01b, paA.x * tA00b)));

        // interp voxel B
        float tB00a = fmaf(pbB.y, b00.y, pbB.x * b00.x);
        float tB00b = fmaf(pbB.y, b00.w, pbB.x * b00.z);
        float tB01a = fmaf(pbB.y, b01.y, pbB.x * b01.x);
        float tB01b = fmaf(pbB.y, b01.w, pbB.x * b01.z);
        float tB10a = fmaf(pbB.y, b10.y, pbB.x * b10.x);
        float tB10b = fmaf(pbB.y, b10.w, pbB.x * b10.z);
        float tB11a = fmaf(pbB.y, b11.y, pbB.x * b11.x);
        float tB11b = fmaf(pbB.y, b11.w, pbB.x * b11.z);
        float sB0 = fmaf(paB.w, tB11a, fmaf(paB.z, tB10a, fmaf(paB.y, tB01a, paB.x * tB00a)));
        float sB1 = fmaf(paB.w, tB11b, fmaf(paB.z, tB10b, fmaf(paB.y, tB01b, paB.x * tB00b)));

        // conv accumulate: one weight load serves both voxels
        const float4* wr = sm4 + WS_BASE + t*64 + cpart;
#pragma unroll
        for (int q = 0; q < 8; q++) {
            float4 wq = wr[q * 8];
            accA[2*q]     = fmaf(wq.x, sA0, fmaf(wq.z, sA1, accA[2*q]));
            accA[2*q + 1] = fmaf(wq.y, sA0, fmaf(wq.w, sA1, accA[2*q + 1]));
            accB[2*q]     = fmaf(wq.x, sB0, fmaf(wq.z, sB1, accB[2*q]));
            accB[2*q + 1] = fmaf(wq.y, sB0, fmaf(wq.w, sB1, accB[2*q + 1]));
        }
    }

    // ---- reduce partial ci sums across the 8 lanes of each voxel
#pragma unroll
    for (int co = 0; co < 16; co++) {
        accA[co] += __shfl_xor_sync(0xffffffffu, accA[co], 1);
        accA[co] += __shfl_xor_sync(0xffffffffu, accA[co], 2);
        accA[co] += __shfl_xor_sync(0xffffffffu, accA[co], 4);
        accB[co] += __shfl_xor_sync(0xffffffffu, accB[co], 1);
        accB[co] += __shfl_xor_sync(0xffffffffu, accB[co], 2);
        accB[co] += __shfl_xor_sync(0xffffffffu, accB[co], 4);
    }
    int co0 = 2 * cpart;
    out[ co0      * VOX + vA] = accA[co0];
    out[(co0 + 1) * VOX + vA] = accA[co0 + 1];
    out[ co0      * VOX + vB] = accB[co0];
    out[(co0 + 1) * VOX + vB] = accB[co0 + 1];
}

// ---------------------------------------------------------------------------
extern "C" void kernel_launch(void* const* d_in, const int* in_sizes, int n_in,
                              void* d_out, int out_size) {
    const float* x   = (const float*)d_in[0];   // [1,16,32,32,32]
    const float* off = (const float*)d_in[1];   // [1,81,32,32,32]
    const float* wgt = (const float*)d_in[2];   // [16,16,3,3,3]
    float* out = (float*)d_out;                 // [1,16,32,32,32]

    cudaFuncSetAttribute(deform_conv3d_kernel,
                         cudaFuncAttributeMaxDynamicSharedMemorySize,
                         SMEM_F4 * 16);

    pad_pairs_kernel<<<(SP*SP*PZ*8 + 255) / 256, 256>>>(x);
    deform_conv3d_kernel<<<VOX / 64, 256, SMEM_F4 * 16>>>(off, wgt, out);
}